// round 2
// baseline (speedup 1.0000x reference)
#include <cuda_runtime.h>
#include <math.h>

// ---------------------------------------------------------------------------
// RegionOutputLayer: conv3x3(512->512)+BN+SiLU, conv1x1(512->425), YOLO decode
// B=16, H=W=40, NSP = 25600 spatial positions.
//
// conv1: implicit GEMM as 9 shifted 1x1 GEMMs (M=512, N=25600, K=512 per tap)
// conv2: GEMM (M=425 padded to 512, N=25600, K=512)
// Both use tf32 mma.sync m16n8k8, fp32 accumulate, RNA tf32 rounding.
// ---------------------------------------------------------------------------

namespace {
constexpr int CIN  = 512;
constexpr int CMID = 512;
constexpr int COUT = 425;
constexpr int NSP  = 25600;          // 16*40*40
constexpr int BM = 128, BN = 160, BK = 32;
constexpr int ASTR = 136;            // padded smem strides (bank-conflict free)
constexpr int BSTR = 168;
constexpr int ABUF = BK * ASTR;      // words per A buffer
constexpr int BBUF = BK * BSTR;      // words per B buffer
constexpr int SMEM_BYTES = (2 * ABUF + 2 * BBUF) * 4;   // 77824 B
}

// scratch (static device allocations are the allowed scratch mechanism)
__device__ float g_w1t[9 * CIN * CMID];          // [tap][cin][cmid]
__device__ float g_w2t[CIN * 512];               // [cin][cout padded to 512]
__device__ float g_s1[CMID];                     // BN scale
__device__ float g_b1[CMID];                     // BN shift
__device__ float g_h[(size_t)CMID * NSP];        // [cmid][n]
__device__ float g_det[(size_t)COUT * NSP];      // [cout][n]

static __device__ __forceinline__ unsigned f2tf32(float f) {
    unsigned u;
    asm("cvt.rna.tf32.f32 %0, %1;" : "=r"(u) : "f"(f));
    return u;
}

static __device__ __forceinline__ void mma8(float* c, const unsigned* a,
                                            unsigned b0, unsigned b1) {
    asm volatile(
        "mma.sync.aligned.m16n8k8.row.col.f32.tf32.tf32.f32 "
        "{%0,%1,%2,%3},{%4,%5,%6,%7},{%8,%9},{%0,%1,%2,%3};"
        : "+f"(c[0]), "+f"(c[1]), "+f"(c[2]), "+f"(c[3])
        : "r"(a[0]), "r"(a[1]), "r"(a[2]), "r"(a[3]), "r"(b0), "r"(b1));
}

static __device__ __forceinline__ float siluf(float x) {
    return x / (1.f + expf(-x));
}
static __device__ __forceinline__ float sigmoidf_(float x) {
    return 1.f / (1.f + expf(-x));
}

// ---------------------------------------------------------------------------
// prep: transpose weights, fold BN into scale/shift
// ---------------------------------------------------------------------------
__global__ void prep_kernel(const float* __restrict__ w1, const float* __restrict__ w2,
                            const float* __restrict__ gamma, const float* __restrict__ beta,
                            const float* __restrict__ mean, const float* __restrict__ var) {
    int i = blockIdx.x * 256 + threadIdx.x;
    if (i < 9 * CIN * CMID) {
        int cmid = i & 511;
        int cin  = (i >> 9) & 511;
        int tap  = i >> 18;
        g_w1t[i] = w1[(cmid * CIN + cin) * 9 + tap];
    }
    if (i < CIN * 512) {
        int cout = i & 511;
        int cin  = i >> 9;
        g_w2t[i] = (cout < COUT) ? w2[cout * CIN + cin] : 0.f;
    }
    if (i < CMID) {
        float s = gamma[i] * rsqrtf(var[i] + 1e-5f);
        g_s1[i] = s;
        g_b1[i] = beta[i] - mean[i] * s;
    }
}

// ---------------------------------------------------------------------------
// GEMM kernel (conv1 implicit 3x3 or conv2 1x1), tf32 mma.sync
// grid (160, 4), block 256 (8 warps: 4 m-warps x 2 n-warps)
// ---------------------------------------------------------------------------
template <bool CONV1>
__global__ void __launch_bounds__(256, 1)
conv_gemm(const float* __restrict__ xin, const float* __restrict__ bias2) {
    extern __shared__ unsigned smem[];
    unsigned* As = smem;
    unsigned* Bs = smem + 2 * ABUF;

    const int tid  = threadIdx.x;
    const int lane = tid & 31;
    const int warp = tid >> 5;
    const int wm   = (warp & 3) << 5;   // 32 rows per m-warp
    const int wn   = (warp >> 2) * 80;  // 80 cols per n-warp
    const int cmid0 = blockIdx.y * BM;
    const int n0    = blockIdx.x * BN;
    const int bimg  = blockIdx.x / 10;          // 10 n-tiles per image
    const int y0    = (blockIdx.x % 10) * 4;    // 4 rows per n-tile
    constexpr int S = CONV1 ? 144 : 16;         // 9 taps * 16 k-blocks | 16 k-blocks

    float acc[2][10][4];
#pragma unroll
    for (int i = 0; i < 2; i++)
#pragma unroll
        for (int j = 0; j < 10; j++)
#pragma unroll
            for (int k = 0; k < 4; k++) acc[i][j][k] = 0.f;

    float4 aR[4];
    float  bR[20];

    const float* bimgbase = CONV1 ? (xin + (size_t)bimg * CIN * 1600) : g_h;

    auto LOAD_A = [&](int s) {
        const float* ap;
        if (CONV1)
            ap = g_w1t + ((size_t)(s >> 4) * CIN + (size_t)(s & 15) * BK) * 512 + cmid0;
        else
            ap = g_w2t + (size_t)s * BK * 512 + cmid0;
#pragma unroll
        for (int j = 0; j < 4; j++) {
            int krel = (tid >> 5) + j * 8;
            int m    = (tid & 31) * 4;
            aR[j] = *reinterpret_cast<const float4*>(ap + krel * 512 + m);
        }
    };
    auto STORE_A = [&](int buf) {
        unsigned* ab = As + buf * ABUF;
#pragma unroll
        for (int j = 0; j < 4; j++) {
            int krel = (tid >> 5) + j * 8;
            int m    = (tid & 31) * 4;
            uint4 u = make_uint4(f2tf32(aR[j].x), f2tf32(aR[j].y),
                                 f2tf32(aR[j].z), f2tf32(aR[j].w));
            *reinterpret_cast<uint4*>(ab + krel * ASTR + m) = u;
        }
    };
    auto LOAD_B = [&](int s) {
        if (CONV1) {
            int tap = s >> 4;
            int dy1 = tap / 3 - 1;
            int dx1 = tap - (tap / 3) * 3 - 1;
            const float* bp = bimgbase + (size_t)((s & 15) * BK) * 1600;
            int krel = tid / 160;
            int rem  = tid - krel * 160;
            int yl   = rem / 40;
            int xl   = rem - yl * 40;
#pragma unroll
            for (int j = 0; j < 20; j++) {
                int yy = y0 + yl + dy1;
                int xx = xl + dx1;
                float v = 0.f;
                if ((unsigned)yy < 40u && (unsigned)xx < 40u)
                    v = __ldg(bp + krel * 1600 + yy * 40 + xx);
                bR[j] = v;
                krel += 1; yl += 2; xl += 16;           // advance by 256 positions
                if (xl >= 40) { xl -= 40; yl += 1; }
                if (yl >= 4)  { yl -= 4;  krel += 1; }
            }
        } else {
            const float* bp = g_h + (size_t)(s * BK) * NSP + n0;
#pragma unroll
            for (int j = 0; j < 5; j++) {
                int id   = tid + j * 256;
                int krel = id / 40;
                int n4   = id - krel * 40;
                *reinterpret_cast<float4*>(&bR[j * 4]) =
                    *reinterpret_cast<const float4*>(bp + (size_t)krel * NSP + n4 * 4);
            }
        }
    };
    auto STORE_B = [&](int buf) {
        unsigned* bb = Bs + buf * BBUF;
        if (CONV1) {
            int krel = tid / 160;
            int rem  = tid - krel * 160;
            int yl   = rem / 40;
            int xl   = rem - yl * 40;
#pragma unroll
            for (int j = 0; j < 20; j++) {
                bb[krel * BSTR + yl * 40 + xl] = f2tf32(bR[j]);
                krel += 1; yl += 2; xl += 16;
                if (xl >= 40) { xl -= 40; yl += 1; }
                if (yl >= 4)  { yl -= 4;  krel += 1; }
            }
        } else {
#pragma unroll
            for (int j = 0; j < 5; j++) {
                int id   = tid + j * 256;
                int krel = id / 40;
                int n4   = id - krel * 40;
                uint4 u = make_uint4(f2tf32(bR[j * 4 + 0]), f2tf32(bR[j * 4 + 1]),
                                     f2tf32(bR[j * 4 + 2]), f2tf32(bR[j * 4 + 3]));
                *reinterpret_cast<uint4*>(bb + krel * BSTR + n4 * 4) = u;
            }
        }
    };
    auto COMPUTE = [&](int buf) {
        const unsigned* ab = As + buf * ABUF;
        const unsigned* bb = Bs + buf * BBUF;
#pragma unroll
        for (int k8 = 0; k8 < 4; k8++) {
            int klo = k8 * 8 + (lane & 3);
            unsigned afr[2][4];
#pragma unroll
            for (int mf = 0; mf < 2; mf++) {
                int m = wm + mf * 16 + (lane >> 2);
                afr[mf][0] = ab[klo * ASTR + m];
                afr[mf][1] = ab[klo * ASTR + m + 8];
                afr[mf][2] = ab[(klo + 4) * ASTR + m];
                afr[mf][3] = ab[(klo + 4) * ASTR + m + 8];
            }
#pragma unroll
            for (int nf = 0; nf < 10; nf++) {
                int n = wn + nf * 8 + (lane >> 2);
                unsigned b0 = bb[klo * BSTR + n];
                unsigned b1 = bb[(klo + 4) * BSTR + n];
                mma8(acc[0][nf], afr[0], b0, b1);
                mma8(acc[1][nf], afr[1], b0, b1);
            }
        }
    };

    LOAD_A(0); LOAD_B(0);
    STORE_A(0); STORE_B(0);
    __syncthreads();
    for (int s = 0; s < S; ++s) {
        if (s + 1 < S) { LOAD_A(s + 1); LOAD_B(s + 1); }
        COMPUTE(s & 1);
        __syncthreads();
        if (s + 1 < S) {
            STORE_A((s + 1) & 1); STORE_B((s + 1) & 1);
            __syncthreads();
        }
    }

    // epilogue
#pragma unroll
    for (int mf = 0; mf < 2; mf++) {
        int r0 = cmid0 + wm + mf * 16 + (lane >> 2);
        int r1 = r0 + 8;
        if (CONV1) {
            float sA = g_s1[r0], bA = g_b1[r0];
            float sB = g_s1[r1], bB = g_b1[r1];
#pragma unroll
            for (int nf = 0; nf < 10; nf++) {
                int col = n0 + wn + nf * 8 + (lane & 3) * 2;
                float2 v01 = make_float2(siluf(acc[mf][nf][0] * sA + bA),
                                         siluf(acc[mf][nf][1] * sA + bA));
                float2 v23 = make_float2(siluf(acc[mf][nf][2] * sB + bB),
                                         siluf(acc[mf][nf][3] * sB + bB));
                *reinterpret_cast<float2*>(&g_h[(size_t)r0 * NSP + col]) = v01;
                *reinterpret_cast<float2*>(&g_h[(size_t)r1 * NSP + col]) = v23;
            }
        } else {
            float bA = (r0 < COUT) ? bias2[r0] : 0.f;
            float bB = (r1 < COUT) ? bias2[r1] : 0.f;
#pragma unroll
            for (int nf = 0; nf < 10; nf++) {
                int col = n0 + wn + nf * 8 + (lane & 3) * 2;
                if (r0 < COUT) {
                    float2 v = make_float2(acc[mf][nf][0] + bA, acc[mf][nf][1] + bA);
                    *reinterpret_cast<float2*>(&g_det[(size_t)r0 * NSP + col]) = v;
                }
                if (r1 < COUT) {
                    float2 v = make_float2(acc[mf][nf][2] + bB, acc[mf][nf][3] + bB);
                    *reinterpret_cast<float2*>(&g_det[(size_t)r1 * NSP + col]) = v;
                }
            }
        }
    }
}

// ---------------------------------------------------------------------------
// decode: boxes / objectness / softmax classes
// out layout: boxes [0,512000) | obj [512000,640000) | classes [640000,10880000)
// ---------------------------------------------------------------------------
__global__ void decode_kernel(const float* __restrict__ anchors, float* __restrict__ out) {
    int idx = blockIdx.x * blockDim.x + threadIdx.x;
    if (idx >= 5 * NSP) return;
    int n = idx % NSP;       // b*1600 + y*40 + x  (coalesced across threads)
    int a = idx / NSP;

    const float* dp = g_det + (size_t)(a * 85) * NSP + n;
    float d0 = dp[0];
    float d1 = dp[(size_t)1 * NSP];
    float d2 = dp[(size_t)2 * NSP];
    float d3 = dp[(size_t)3 * NSP];
    float d4 = dp[(size_t)4 * NSP];

    float cls[80];
    float mx = -1e30f;
#pragma unroll
    for (int c = 0; c < 80; c++) {
        float v = dp[(size_t)(5 + c) * NSP];
        cls[c] = v;
        mx = fmaxf(mx, v);
    }
    float sum = 0.f;
#pragma unroll
    for (int c = 0; c < 80; c++) {
        float e = expf(cls[c] - mx);
        cls[c] = e;
        sum += e;
    }
    float inv = 1.f / sum;

    int x = n % 40;
    int y = (n / 40) % 40;
    float bx = ((float)x + sigmoidf_(d0)) * (1.f / 40.f);
    float by = ((float)y + sigmoidf_(d1)) * (1.f / 40.f);
    float bw = anchors[2 * a]     * expf(d2);
    float bh = anchors[2 * a + 1] * expf(d3);

    *reinterpret_cast<float4*>(&out[(size_t)(n * 5 + a) * 4]) = make_float4(bx, by, bw, bh);
    out[512000 + n * 5 + a] = sigmoidf_(d4);

    float* co = out + 640000 + (size_t)(n * 5 + a) * 80;
#pragma unroll
    for (int c = 0; c < 80; c += 4) {
        *reinterpret_cast<float4*>(&co[c]) =
            make_float4(cls[c] * inv, cls[c + 1] * inv, cls[c + 2] * inv, cls[c + 3] * inv);
    }
}

// ---------------------------------------------------------------------------
extern "C" void kernel_launch(void* const* d_in, const int* in_sizes, int n_in,
                              void* d_out, int out_size) {
    const float* x       = (const float*)d_in[0];
    const float* w1      = (const float*)d_in[1];
    const float* gamma   = (const float*)d_in[2];
    const float* beta    = (const float*)d_in[3];
    const float* mean    = (const float*)d_in[4];
    const float* var     = (const float*)d_in[5];
    const float* w2      = (const float*)d_in[6];
    const float* b2      = (const float*)d_in[7];
    const float* anchors = (const float*)d_in[8];
    float* out = (float*)d_out;

    cudaFuncSetAttribute(conv_gemm<true>,  cudaFuncAttributeMaxDynamicSharedMemorySize, SMEM_BYTES);
    cudaFuncSetAttribute(conv_gemm<false>, cudaFuncAttributeMaxDynamicSharedMemorySize, SMEM_BYTES);

    prep_kernel<<<(9 * CIN * CMID + 255) / 256, 256>>>(w1, w2, gamma, beta, mean, var);
    conv_gemm<true><<<dim3(160, 4), 256, SMEM_BYTES>>>(x, nullptr);
    conv_gemm<false><<<dim3(160, 4), 256, SMEM_BYTES>>>(nullptr, b2);
    decode_kernel<<<(5 * NSP + 255) / 256, 256>>>(anchors, out);
}

// round 4
// speedup vs baseline: 2.6764x; 2.6764x over previous
#include <cuda_runtime.h>
#include <cuda_fp16.h>
#include <math.h>
#include <stdint.h>

// RegionOutputLayer via fp16 mma.sync (m16n8k16) — compute_100-safe (no tcgen05)
// Layout: activations [spatial_padded][channel] fp16; weights [tap][cout][cin] fp16.
// conv1 = 9 shifted GEMMs (M=spatial, N=cmid, K=cin), conv2 = 1 GEMM.

namespace {
constexpr int COUT = 425;
constexpr int BATCH = 16, HH = 40, WW = 40;
constexpr int PW = 42, PPI = 42 * 42;      // 1764
constexpr int P = BATCH * PPI;             // 28224
constexpr int NSP = BATCH * HH * WW;       // 25600
constexpr int GPRE = 64;                   // guard rows before
constexpr int PROWS = GPRE + P + 128;      // 28416
constexpr int MROWS = 28288;               // 221*128
constexpr int MTILES = 221;
constexpr int BM = 128, BN = 128, BK = 64;
constexpr int TILE_BYTES = BM * BK * 2;    // 16384
constexpr int STAGE_BYTES = 2 * TILE_BYTES;
constexpr int NSLOT = 3;
constexpr int SMEM_BYTES = NSLOT * STAGE_BYTES;   // 98304
}

__device__ __align__(128) __half g_xp[(size_t)PROWS * 512];
__device__ __align__(128) __half g_h [(size_t)MROWS * 512];
__device__ __align__(128) __half g_w1t[9 * 512 * 512];   // [tap][cout][cin]
__device__ __align__(128) __half g_w2t[512 * 512];       // [cout pad][cin]
__device__ __align__(128) float  g_det[(size_t)MROWS * 512];
__device__ float g_s1[512], g_b1[512];

static __device__ __forceinline__ uint32_t s2u(const void* p) {
    uint32_t a;
    asm("{ .reg .u64 t; cvta.to.shared.u64 t, %1; cvt.u32.u64 %0, t; }" : "=r"(a) : "l"(p));
    return a;
}
static __device__ __forceinline__ void cpa16(uint32_t dst, const void* src) {
    asm volatile("cp.async.cg.shared.global [%0], [%1], 16;"
                 :: "r"(dst), "l"(__cvta_generic_to_global(src)));
}
#define CP_COMMIT() asm volatile("cp.async.commit_group;" ::: "memory")
#define CP_WAIT(n)  asm volatile("cp.async.wait_group %0;" :: "n"(n) : "memory")
#define LDSM4(r, a) \
    asm volatile("ldmatrix.sync.aligned.m8n8.x4.shared.b16 {%0,%1,%2,%3}, [%4];" \
                 : "=r"((r)[0]), "=r"((r)[1]), "=r"((r)[2]), "=r"((r)[3]) : "r"(a))
#define MMA16(c, a, b0, b1) \
    asm volatile("mma.sync.aligned.m16n8k16.row.col.f32.f16.f16.f32 " \
                 "{%0,%1,%2,%3},{%4,%5,%6,%7},{%8,%9},{%0,%1,%2,%3};" \
                 : "+f"((c)[0]), "+f"((c)[1]), "+f"((c)[2]), "+f"((c)[3]) \
                 : "r"((a)[0]), "r"((a)[1]), "r"((a)[2]), "r"((a)[3]), "r"(b0), "r"(b1))

// ------------------------------- prep ------------------------------------
__global__ void prep_w(const float* __restrict__ w1, const float* __restrict__ w2,
                       const float* __restrict__ gamma, const float* __restrict__ beta,
                       const float* __restrict__ mean, const float* __restrict__ var) {
    int i = blockIdx.x * 256 + threadIdx.x;
    if (i < 9 * 512 * 512) {
        int tap = i / (512 * 512);
        int r = i % (512 * 512);          // r = cm*512 + ci
        g_w1t[i] = __float2half_rn(w1[(size_t)r * 9 + tap]);
    }
    if (i < 512 * 512) {
        int co = i >> 9, ci = i & 511;
        g_w2t[i] = __float2half_rn(co < COUT ? w2[co * 512 + ci] : 0.f);
    }
    if (i < 512) {
        float s = gamma[i] * rsqrtf(var[i] + 1e-5f);
        g_s1[i] = s;
        g_b1[i] = beta[i] - mean[i] * s;
    }
}

__global__ void prep_x(const float* __restrict__ x) {
    __shared__ float s[64][41];
    int c0 = blockIdx.x * 64, yp = blockIdx.y, b = blockIdx.z;
    int tid = threadIdx.x;
    int y = yp - 1;
    bool interior = (y >= 0 && y < HH);
    if (interior)
        for (int i = tid; i < 64 * 40; i += 256) {
            int c = i / 40, xx = i % 40;
            s[c][xx] = x[(((size_t)b * 512 + c0 + c) * HH + y) * WW + xx];
        }
    __syncthreads();
    size_t pbase = (size_t)GPRE + (size_t)b * PPI + (size_t)yp * PW;
    for (int i = tid; i < 42 * 64; i += 256) {
        int xp = i >> 6, c = i & 63;
        float v = (interior && xp >= 1 && xp <= 40) ? s[c][xp - 1] : 0.f;
        g_xp[(pbase + xp) * 512 + c0 + c] = __float2half_rn(v);
    }
}

// ------------------------------- conv ------------------------------------
template <int TAPS, bool CONV1>
__global__ void __launch_bounds__(256)
conv_mma(const float* __restrict__ bias2) {
    extern __shared__ __align__(128) __half smem[];
    const uint32_t sbase = s2u(smem);
    const int tid = threadIdx.x, lane = tid & 31, warp = tid >> 5;
    const int wm = (warp & 1) * 64;          // 2 m-warps x 64 rows
    const int wn = (warp >> 1) * 32;         // 4 n-warps x 32 cols
    const int n0 = blockIdx.x * BN;
    const int p0 = blockIdx.y * BM;
    constexpr int S = TAPS * 8;

    const __half* Aglob = CONV1 ? (g_xp + (size_t)GPRE * 512) : g_h;
    const __half* Bglob = CONV1 ? g_w1t : g_w2t;

    float acc[4][4][4];
#pragma unroll
    for (int i = 0; i < 4; i++)
#pragma unroll
        for (int j = 0; j < 4; j++)
#pragma unroll
            for (int k = 0; k < 4; k++) acc[i][j][k] = 0.f;

    auto LOADSTAGE = [&](int s) {
        int slot = s % NSLOT;
        uint32_t dstA = sbase + slot * STAGE_BYTES;
        uint32_t dstB = dstA + TILE_BYTES;
        int tap = CONV1 ? (s >> 3) : 0;
        int kc = (s & 7) * 64;
        int shift = CONV1 ? ((tap / 3 - 1) * PW + (tap % 3 - 1)) : 0;
        const __half* srcA = Aglob + (size_t)(p0 + shift) * 512 + kc;
        const __half* srcB = Bglob + ((size_t)tap * 512 + n0) * 512 + kc;
#pragma unroll
        for (int u = 0; u < 4; u++) {
            int q = tid + u * 256;
            int r = q >> 3, c = q & 7;
            cpa16(dstA + r * 128 + ((c ^ (r & 7)) * 16), srcA + (size_t)r * 512 + c * 8);
        }
#pragma unroll
        for (int u = 0; u < 4; u++) {
            int q = tid + u * 256;
            int r = q >> 3, c = q & 7;
            cpa16(dstB + r * 128 + ((c ^ (r & 7)) * 16), srcB + (size_t)r * 512 + c * 8);
        }
        CP_COMMIT();
    };

    // ldmatrix per-thread row/chunk bases
    const int rA = wm + (lane & 15);
    const int hiA = lane >> 4;
    const int rB = wn + (lane & 7) + ((lane & 16) >> 1);
    const int hiB = (lane >> 3) & 1;

    auto COMPUTE = [&](int slot) {
        uint32_t Ab = sbase + slot * STAGE_BYTES;
        uint32_t Bb = Ab + TILE_BYTES;
#pragma unroll
        for (int ks = 0; ks < 4; ks++) {
            uint32_t a[4][4], b[2][4];
#pragma unroll
            for (int i = 0; i < 4; i++) {
                int r = rA + 16 * i;
                LDSM4(a[i], Ab + r * 128 + (((2 * ks + hiA) ^ (r & 7)) * 16));
            }
#pragma unroll
            for (int pr = 0; pr < 2; pr++) {
                int r = rB + 16 * pr;
                LDSM4(b[pr], Bb + r * 128 + (((2 * ks + hiB) ^ (r & 7)) * 16));
            }
#pragma unroll
            for (int i = 0; i < 4; i++)
#pragma unroll
                for (int j = 0; j < 4; j++)
                    MMA16(acc[i][j], a[i], b[j >> 1][(j & 1) * 2], b[j >> 1][(j & 1) * 2 + 1]);
        }
    };

    LOADSTAGE(0);
    LOADSTAGE(1);
    for (int s = 0; s < S; s++) {
        if (s + 2 < S) CP_WAIT(1); else CP_WAIT(0);
        __syncthreads();
        if (s + 2 < S) LOADSTAGE(s + 2);
        COMPUTE(s % NSLOT);
    }

    // epilogue: scales/bias staged in (now free) smem
    __syncthreads();
    float* ssc = reinterpret_cast<float*>(smem);
    float* ssh = ssc + 128;
    if (tid < 128) {
        int c = n0 + tid;
        if (CONV1) { ssc[tid] = g_s1[c]; ssh[tid] = g_b1[c]; }
        else       { ssh[tid] = (c < COUT) ? bias2[c] : 0.f; }
    }
    __syncthreads();

    const int g = lane >> 2, t = lane & 3;
#pragma unroll
    for (int i = 0; i < 4; i++) {
#pragma unroll
        for (int j = 0; j < 4; j++) {
            int cl = wn + 8 * j + 2 * t;           // local col of pair
            int ch = n0 + cl;
#pragma unroll
            for (int hf = 0; hf < 2; hf++) {
                int row = p0 + wm + 16 * i + g + hf * 8;
                float v0 = acc[i][j][hf * 2 + 0];
                float v1 = acc[i][j][hf * 2 + 1];
                if (CONV1) {
                    v0 = fmaf(v0, ssc[cl], ssh[cl]);
                    v1 = fmaf(v1, ssc[cl + 1], ssh[cl + 1]);
                    v0 = v0 / (1.f + expf(-v0));
                    v1 = v1 / (1.f + expf(-v1));
                    *reinterpret_cast<__half2*>(&g_h[(size_t)row * 512 + ch]) =
                        __floats2half2_rn(v0, v1);
                } else {
                    *reinterpret_cast<float2*>(&g_det[(size_t)row * 512 + ch]) =
                        make_float2(v0 + ssh[cl], v1 + ssh[cl + 1]);
                }
            }
        }
    }
}

// ------------------------------- decode ----------------------------------
__global__ void decode_kernel(const float* __restrict__ anchors, float* __restrict__ out) {
    int idx = blockIdx.x * blockDim.x + threadIdx.x;
    if (idx >= 5 * NSP) return;
    int n = idx % NSP, a = idx / NSP;
    int b = n / 1600, rem = n % 1600, y = rem / 40, x = rem % 40;
    size_t pp = (size_t)b * PPI + (size_t)(y + 1) * PW + (x + 1);
    const float* dp = g_det + pp * 512 + a * 85;

    float d0 = dp[0], d1 = dp[1], d2 = dp[2], d3 = dp[3], d4 = dp[4];
    float cls[80], mx = -1e30f;
#pragma unroll
    for (int c = 0; c < 80; c++) { cls[c] = __ldg(dp + 5 + c); mx = fmaxf(mx, cls[c]); }
    float sum = 0.f;
#pragma unroll
    for (int c = 0; c < 80; c++) { cls[c] = expf(cls[c] - mx); sum += cls[c]; }
    float inv = 1.f / sum;

    float bx = ((float)x + 1.f / (1.f + expf(-d0))) * (1.f / 40.f);
    float by = ((float)y + 1.f / (1.f + expf(-d1))) * (1.f / 40.f);
    float bw = __ldg(anchors + 2 * a)     * expf(d2);
    float bh = __ldg(anchors + 2 * a + 1) * expf(d3);

    *reinterpret_cast<float4*>(&out[(size_t)(n * 5 + a) * 4]) = make_float4(bx, by, bw, bh);
    out[512000 + n * 5 + a] = 1.f / (1.f + expf(-d4));
    float* co = out + 640000 + (size_t)(n * 5 + a) * 80;
#pragma unroll
    for (int c = 0; c < 80; c += 4)
        *reinterpret_cast<float4*>(&co[c]) = make_float4(cls[c] * inv, cls[c + 1] * inv,
                                                         cls[c + 2] * inv, cls[c + 3] * inv);
}

// ------------------------------- host ------------------------------------
extern "C" void kernel_launch(void* const* d_in, const int* in_sizes, int n_in,
                              void* d_out, int out_size) {
    const float* x       = (const float*)d_in[0];
    const float* w1      = (const float*)d_in[1];
    const float* gamma   = (const float*)d_in[2];
    const float* beta    = (const float*)d_in[3];
    const float* mean    = (const float*)d_in[4];
    const float* var     = (const float*)d_in[5];
    const float* w2      = (const float*)d_in[6];
    const float* b2      = (const float*)d_in[7];
    const float* anchors = (const float*)d_in[8];
    float* out = (float*)d_out;

    cudaFuncSetAttribute(conv_mma<9, true>,  cudaFuncAttributeMaxDynamicSharedMemorySize, SMEM_BYTES);
    cudaFuncSetAttribute(conv_mma<1, false>, cudaFuncAttributeMaxDynamicSharedMemorySize, SMEM_BYTES);

    prep_w<<<(9 * 512 * 512 + 255) / 256, 256>>>(w1, w2, gamma, beta, mean, var);
    prep_x<<<dim3(8, 42, 16), 256>>>(x);
    conv_mma<9, true><<<dim3(4, MTILES), 256, SMEM_BYTES>>>(nullptr);
    conv_mma<1, false><<<dim3(4, MTILES), 256, SMEM_BYTES>>>(b2);
    decode_kernel<<<(5 * NSP + 255) / 256, 256>>>(anchors, out);
}

// round 5
// speedup vs baseline: 3.3980x; 1.2696x over previous
#include <cuda_runtime.h>
#include <cuda_fp16.h>
#include <math.h>
#include <stdint.h>

// RegionOutputLayer via fp16 mma.sync (m16n8k16), compute_100-safe.
// conv1: kc-outer / tap-inner with 216-row A-halo loaded once per kc.
// conv2: classic 3-slot pipelined GEMM. decode: smem-staged coalesced.

namespace {
constexpr int COUT = 425;
constexpr int BATCH = 16, HH = 40, WW = 40;
constexpr int PW = 42, PPI = 42 * 42;      // 1764
constexpr int P = BATCH * PPI;             // 28224
constexpr int NSP = BATCH * HH * WW;       // 25600
constexpr int GPRE = 64;
constexpr int PROWS = GPRE + P + 128;      // 28416
constexpr int MROWS = 28288;               // 221*128
constexpr int MTILES = 221;

// conv1 halo pipeline
constexpr int HALO = 216;                  // 128 + 2*43 rounded up (offset 44)
constexpr int ABYTES = HALO * 128;         // 27648
constexpr int BBYTES = 16384;              // 128 rows x 64 ch fp16
constexpr int SMEM1 = 2 * ABYTES + 3 * BBYTES;   // 104448

// conv2 pipeline
constexpr int TILE2 = 16384;
constexpr int STAGE2 = 2 * TILE2;
constexpr int SMEM2 = 3 * STAGE2;          // 98304

constexpr int DEC_STRIDE = 436;
constexpr int SMEM_DEC = 40 * DEC_STRIDE * 4;    // 69760
}

__device__ __align__(128) __half g_xp[(size_t)PROWS * 512];
__device__ __align__(128) __half g_h [(size_t)MROWS * 512];
__device__ __align__(128) __half g_w1t[9 * 512 * 512];   // [tap][cout][cin]
__device__ __align__(128) __half g_w2t[512 * 512];       // [cout pad][cin]
__device__ __align__(128) float  g_det[(size_t)MROWS * 512];
__device__ float g_s1[512], g_b1[512];

static __device__ __forceinline__ uint32_t s2u(const void* p) {
    uint32_t a;
    asm("{ .reg .u64 t; cvta.to.shared.u64 t, %1; cvt.u32.u64 %0, t; }" : "=r"(a) : "l"(p));
    return a;
}
static __device__ __forceinline__ void cpa16(uint32_t dst, const void* src) {
    asm volatile("cp.async.cg.shared.global [%0], [%1], 16;"
                 :: "r"(dst), "l"(__cvta_generic_to_global(src)));
}
#define CP_COMMIT() asm volatile("cp.async.commit_group;" ::: "memory")
#define CP_WAIT(n)  asm volatile("cp.async.wait_group %0;" :: "n"(n) : "memory")
#define LDSM4(r, a) \
    asm volatile("ldmatrix.sync.aligned.m8n8.x4.shared.b16 {%0,%1,%2,%3}, [%4];" \
                 : "=r"((r)[0]), "=r"((r)[1]), "=r"((r)[2]), "=r"((r)[3]) : "r"(a))
#define MMA16(c, a, b0, b1) \
    asm volatile("mma.sync.aligned.m16n8k16.row.col.f32.f16.f16.f32 " \
                 "{%0,%1,%2,%3},{%4,%5,%6,%7},{%8,%9},{%0,%1,%2,%3};" \
                 : "+f"((c)[0]), "+f"((c)[1]), "+f"((c)[2]), "+f"((c)[3]) \
                 : "r"((a)[0]), "r"((a)[1]), "r"((a)[2]), "r"((a)[3]), "r"(b0), "r"(b1))

// ------------------------------- prep ------------------------------------
__global__ void prep_w(const float* __restrict__ w1, const float* __restrict__ w2,
                       const float* __restrict__ gamma, const float* __restrict__ beta,
                       const float* __restrict__ mean, const float* __restrict__ var) {
    int i = blockIdx.x * 256 + threadIdx.x;
    if (i < 9 * 512 * 512) {
        int tap = i / (512 * 512);
        int r = i % (512 * 512);          // r = cm*512 + ci
        g_w1t[i] = __float2half_rn(w1[(size_t)r * 9 + tap]);
    }
    if (i < 512 * 512) {
        int co = i >> 9, ci = i & 511;
        g_w2t[i] = __float2half_rn(co < COUT ? w2[co * 512 + ci] : 0.f);
    }
    if (i < 512) {
        float s = gamma[i] * rsqrtf(var[i] + 1e-5f);
        g_s1[i] = s;
        g_b1[i] = beta[i] - mean[i] * s;
    }
}

__global__ void prep_x(const float* __restrict__ x) {
    __shared__ float s[64][41];
    int c0 = blockIdx.x * 64, yp = blockIdx.y, b = blockIdx.z;
    int tid = threadIdx.x;
    int y = yp - 1;
    bool interior = (y >= 0 && y < HH);
    if (interior)
        for (int i = tid; i < 64 * 40; i += 256) {
            int c = i / 40, xx = i % 40;
            s[c][xx] = x[(((size_t)b * 512 + c0 + c) * HH + y) * WW + xx];
        }
    __syncthreads();
    size_t pbase = (size_t)GPRE + (size_t)b * PPI + (size_t)yp * PW;
    for (int i = tid; i < 42 * 64; i += 256) {
        int xp = i >> 6, c = i & 63;
        float v = (interior && xp >= 1 && xp <= 40) ? s[c][xp - 1] : 0.f;
        g_xp[(pbase + xp) * 512 + c0 + c] = __float2half_rn(v);
    }
}

// ------------------------------- conv1 -----------------------------------
__global__ void __launch_bounds__(256, 2)
conv1_mma() {
    extern __shared__ __align__(128) __half smem[];
    const uint32_t sbase = s2u(smem);
    const int tid = threadIdx.x, lane = tid & 31, warp = tid >> 5;
    const int wm = (warp & 1) * 64;
    const int wn = (warp >> 1) * 32;
    const int n0 = blockIdx.x * 128;
    const int p0 = blockIdx.y * 128;

    float acc[4][4][4];
#pragma unroll
    for (int i = 0; i < 4; i++)
#pragma unroll
        for (int j = 0; j < 4; j++)
#pragma unroll
            for (int k = 0; k < 4; k++) acc[i][j][k] = 0.f;

    const __half* Abase = g_xp + (size_t)(GPRE + p0 - 44) * 512;

    auto LOAD_A = [&](int kc, int slot) {
        const __half* src = Abase + kc * 64;
        uint32_t dst = sbase + slot * ABYTES;
#pragma unroll
        for (int u = 0; u < 7; u++) {
            int id = tid + u * 256;
            if (id < HALO * 8) {
                int r = id >> 3, c = id & 7;
                cpa16(dst + r * 128 + ((c ^ (r & 7)) * 16), src + (size_t)r * 512 + c * 8);
            }
        }
    };
    auto LOAD_B = [&](int kc, int tap, int slot) {
        const __half* src = g_w1t + ((size_t)tap * 512 + n0) * 512 + kc * 64;
        uint32_t dst = sbase + 2 * ABYTES + slot * BBYTES;
#pragma unroll
        for (int u = 0; u < 4; u++) {
            int id = tid + u * 256;
            int r = id >> 3, c = id & 7;
            cpa16(dst + r * 128 + ((c ^ (r & 7)) * 16), src + (size_t)r * 512 + c * 8);
        }
    };

    const int rA_base = wm + (lane & 15) + 44;
    const int hiA = lane >> 4;
    const int rB = wn + (lane & 7) + ((lane & 16) >> 1);
    const int hiB = (lane >> 3) & 1;

    auto COMPUTE = [&](int kc, int tap, int bslot) {
        int shift = (tap / 3 - 1) * PW + (tap % 3) - 1;
        uint32_t Ab = sbase + (kc & 1) * ABYTES;
        uint32_t Bb = sbase + 2 * ABYTES + bslot * BBYTES;
#pragma unroll
        for (int ks = 0; ks < 4; ks++) {
            uint32_t a[4][4], b[2][4];
#pragma unroll
            for (int i = 0; i < 4; i++) {
                int r = rA_base + 16 * i + shift;
                LDSM4(a[i], Ab + r * 128 + (((2 * ks + hiA) ^ (r & 7)) * 16));
            }
#pragma unroll
            for (int pr = 0; pr < 2; pr++) {
                int r = rB + 16 * pr;
                LDSM4(b[pr], Bb + r * 128 + (((2 * ks + hiB) ^ (r & 7)) * 16));
            }
#pragma unroll
            for (int i = 0; i < 4; i++)
#pragma unroll
                for (int j = 0; j < 4; j++)
                    MMA16(acc[i][j], a[i], b[j >> 1][(j & 1) * 2], b[j >> 1][(j & 1) * 2 + 1]);
        }
    };

    // prologue: groups G0={A0,B0}, G1={B1}
    LOAD_A(0, 0); LOAD_B(0, 0, 0); CP_COMMIT();
    LOAD_B(0, 1, 1); CP_COMMIT();

    for (int s = 0; s < 72; s++) {
        int kc = s / 9, tap = s - kc * 9;
        CP_WAIT(1);
        __syncthreads();
        int s2 = s + 2;
        if (s2 < 72) LOAD_B(s2 / 9, s2 % 9, s2 % 3);
        if (tap == 0 && kc < 7) LOAD_A(kc + 1, (kc + 1) & 1);
        CP_COMMIT();
        COMPUTE(kc, tap, s % 3);
    }

    __syncthreads();
    float* ssc = reinterpret_cast<float*>(smem);
    float* ssh = ssc + 128;
    if (tid < 128) {
        int c = n0 + tid;
        ssc[tid] = g_s1[c];
        ssh[tid] = g_b1[c];
    }
    __syncthreads();

    const int g = lane >> 2, t = lane & 3;
#pragma unroll
    for (int i = 0; i < 4; i++) {
#pragma unroll
        for (int j = 0; j < 4; j++) {
            int cl = wn + 8 * j + 2 * t;
            int ch = n0 + cl;
#pragma unroll
            for (int hf = 0; hf < 2; hf++) {
                int row = p0 + wm + 16 * i + g + hf * 8;
                float v0 = acc[i][j][hf * 2 + 0];
                float v1 = acc[i][j][hf * 2 + 1];
                v0 = fmaf(v0, ssc[cl], ssh[cl]);
                v1 = fmaf(v1, ssc[cl + 1], ssh[cl + 1]);
                v0 = v0 / (1.f + expf(-v0));
                v1 = v1 / (1.f + expf(-v1));
                *reinterpret_cast<__half2*>(&g_h[(size_t)row * 512 + ch]) =
                    __floats2half2_rn(v0, v1);
            }
        }
    }
}

// ------------------------------- conv2 -----------------------------------
__global__ void __launch_bounds__(256, 2)
conv2_mma(const float* __restrict__ bias2) {
    extern __shared__ __align__(128) __half smem[];
    const uint32_t sbase = s2u(smem);
    const int tid = threadIdx.x, lane = tid & 31, warp = tid >> 5;
    const int wm = (warp & 1) * 64;
    const int wn = (warp >> 1) * 32;
    const int n0 = blockIdx.x * 128;
    const int p0 = blockIdx.y * 128;

    float acc[4][4][4];
#pragma unroll
    for (int i = 0; i < 4; i++)
#pragma unroll
        for (int j = 0; j < 4; j++)
#pragma unroll
            for (int k = 0; k < 4; k++) acc[i][j][k] = 0.f;

    auto LOADSTAGE = [&](int s) {
        int slot = s % 3;
        uint32_t dstA = sbase + slot * STAGE2;
        uint32_t dstB = dstA + TILE2;
        int kc = s * 64;
        const __half* srcA = g_h + (size_t)p0 * 512 + kc;
        const __half* srcB = g_w2t + (size_t)n0 * 512 + kc;
#pragma unroll
        for (int u = 0; u < 4; u++) {
            int q = tid + u * 256;
            int r = q >> 3, c = q & 7;
            cpa16(dstA + r * 128 + ((c ^ (r & 7)) * 16), srcA + (size_t)r * 512 + c * 8);
        }
#pragma unroll
        for (int u = 0; u < 4; u++) {
            int q = tid + u * 256;
            int r = q >> 3, c = q & 7;
            cpa16(dstB + r * 128 + ((c ^ (r & 7)) * 16), srcB + (size_t)r * 512 + c * 8);
        }
        CP_COMMIT();
    };

    const int rA = wm + (lane & 15);
    const int hiA = lane >> 4;
    const int rB = wn + (lane & 7) + ((lane & 16) >> 1);
    const int hiB = (lane >> 3) & 1;

    auto COMPUTE = [&](int slot) {
        uint32_t Ab = sbase + slot * STAGE2;
        uint32_t Bb = Ab + TILE2;
#pragma unroll
        for (int ks = 0; ks < 4; ks++) {
            uint32_t a[4][4], b[2][4];
#pragma unroll
            for (int i = 0; i < 4; i++) {
                int r = rA + 16 * i;
                LDSM4(a[i], Ab + r * 128 + (((2 * ks + hiA) ^ (r & 7)) * 16));
            }
#pragma unroll
            for (int pr = 0; pr < 2; pr++) {
                int r = rB + 16 * pr;
                LDSM4(b[pr], Bb + r * 128 + (((2 * ks + hiB) ^ (r & 7)) * 16));
            }
#pragma unroll
            for (int i = 0; i < 4; i++)
#pragma unroll
                for (int j = 0; j < 4; j++)
                    MMA16(acc[i][j], a[i], b[j >> 1][(j & 1) * 2], b[j >> 1][(j & 1) * 2 + 1]);
        }
    };

    LOADSTAGE(0);
    LOADSTAGE(1);
    for (int s = 0; s < 8; s++) {
        if (s + 2 < 8) CP_WAIT(1); else CP_WAIT(0);
        __syncthreads();
        if (s + 2 < 8) LOADSTAGE(s + 2);
        COMPUTE(s % 3);
    }

    __syncthreads();
    float* ssh = reinterpret_cast<float*>(smem);
    if (tid < 128) {
        int c = n0 + tid;
        ssh[tid] = (c < COUT) ? bias2[c] : 0.f;
    }
    __syncthreads();

    const int g = lane >> 2, t = lane & 3;
#pragma unroll
    for (int i = 0; i < 4; i++) {
#pragma unroll
        for (int j = 0; j < 4; j++) {
            int cl = wn + 8 * j + 2 * t;
            int ch = n0 + cl;
#pragma unroll
            for (int hf = 0; hf < 2; hf++) {
                int row = p0 + wm + 16 * i + g + hf * 8;
                *reinterpret_cast<float2*>(&g_det[(size_t)row * 512 + ch]) =
                    make_float2(acc[i][j][hf * 2 + 0] + ssh[cl],
                                acc[i][j][hf * 2 + 1] + ssh[cl + 1]);
            }
        }
    }
}

// ------------------------------- decode ----------------------------------
__global__ void decode_kernel(const float* __restrict__ anchors, float* __restrict__ out) {
    extern __shared__ float srow[];            // [40][DEC_STRIDE]
    int y = blockIdx.x, b = blockIdx.y;
    int tid = threadIdx.x;

    const float* rowbase = g_det + ((size_t)b * PPI + (size_t)(y + 1) * PW + 1) * 512;
    for (int i = tid; i < 40 * 107; i += 256) {
        int xl = i / 107, q = i - xl * 107;
        *reinterpret_cast<float4*>(&srow[xl * DEC_STRIDE + q * 4]) =
            *reinterpret_cast<const float4*>(rowbase + (size_t)xl * 512 + q * 4);
    }
    __syncthreads();

    if (tid < 200) {
        int xl = tid / 5, a = tid - xl * 5;
        const float* dp = srow + xl * DEC_STRIDE + a * 85;
        float d0 = dp[0], d1 = dp[1], d2 = dp[2], d3 = dp[3], d4 = dp[4];
        float cls[80], mx = -1e30f;
#pragma unroll
        for (int c = 0; c < 80; c++) { cls[c] = dp[5 + c]; mx = fmaxf(mx, cls[c]); }
        float sum = 0.f;
#pragma unroll
        for (int c = 0; c < 80; c++) { cls[c] = expf(cls[c] - mx); sum += cls[c]; }
        float inv = 1.f / sum;

        int n = b * 1600 + y * 40 + xl;
        float bx = ((float)xl + 1.f / (1.f + expf(-d0))) * (1.f / 40.f);
        float by = ((float)y + 1.f / (1.f + expf(-d1))) * (1.f / 40.f);
        float bw = __ldg(anchors + 2 * a)     * expf(d2);
        float bh = __ldg(anchors + 2 * a + 1) * expf(d3);

        *reinterpret_cast<float4*>(&out[(size_t)(n * 5 + a) * 4]) = make_float4(bx, by, bw, bh);
        out[512000 + n * 5 + a] = 1.f / (1.f + expf(-d4));
        float* co = out + 640000 + (size_t)(n * 5 + a) * 80;
#pragma unroll
        for (int c = 0; c < 80; c += 4)
            *reinterpret_cast<float4*>(&co[c]) = make_float4(cls[c] * inv, cls[c + 1] * inv,
                                                             cls[c + 2] * inv, cls[c + 3] * inv);
    }
}

// ------------------------------- host ------------------------------------
extern "C" void kernel_launch(void* const* d_in, const int* in_sizes, int n_in,
                              void* d_out, int out_size) {
    const float* x       = (const float*)d_in[0];
    const float* w1      = (const float*)d_in[1];
    const float* gamma   = (const float*)d_in[2];
    const float* beta    = (const float*)d_in[3];
    const float* mean    = (const float*)d_in[4];
    const float* var     = (const float*)d_in[5];
    const float* w2      = (const float*)d_in[6];
    const float* b2      = (const float*)d_in[7];
    const float* anchors = (const float*)d_in[8];
    float* out = (float*)d_out;

    cudaFuncSetAttribute(conv1_mma,     cudaFuncAttributeMaxDynamicSharedMemorySize, SMEM1);
    cudaFuncSetAttribute(conv2_mma,     cudaFuncAttributeMaxDynamicSharedMemorySize, SMEM2);
    cudaFuncSetAttribute(decode_kernel, cudaFuncAttributeMaxDynamicSharedMemorySize, SMEM_DEC);

    prep_w<<<(9 * 512 * 512 + 255) / 256, 256>>>(w1, w2, gamma, beta, mean, var);
    prep_x<<<dim3(8, 42, 16), 256>>>(x);
    conv1_mma<<<dim3(4, MTILES), 256, SMEM1>>>();
    conv2_mma<<<dim3(4, MTILES), 256, SMEM2>>>(b2);
    decode_kernel<<<dim3(40, 16), 256, SMEM_DEC>>>(anchors, out);
}